// round 3
// baseline (speedup 1.0000x reference)
#include <cuda_runtime.h>

// SequentialConv: B=8, C=64, H=192, W=256, 3x3, sequential row recurrence.
// Persistent wavefront: 8 batches x 16 width-tiles = 128 CTAs (all resident).
// Round 3: fma.rn.f32x2 packed over the co dimension; row buffer stored as
// splatted float2 pairs so every FFMA2 operand is one aligned LDS.64.

#define Bb 8
#define Cc 64
#define Hh 192
#define Ww 256
#define NT 16
#define TW 16
#define NTHR 128
#define RST2 20        // row stride in float2 units (18 used)

#define WSM_FLOATS (Cc * Cc * 9)
#define RBUF2_ELEMS (3 * Cc * RST2)
#define SMEM_BYTES (WSM_FLOATS * 4 + RBUF2_ELEMS * 8 + Cc * 4)

typedef unsigned long long ull;

__device__ __forceinline__ void ffma2(ull& d, ull a, ull b) {
    asm("fma.rn.f32x2 %0, %1, %2, %0;" : "+l"(d) : "l"(a), "l"(b));
}

__device__ int g_flags[Bb * NT];

__global__ void sc_init_flags() {
    int i = threadIdx.x;
    if (i < Bb * NT) g_flags[i] = 1;   // rows 0,1 are complete (unchanged)
}

__global__ void __launch_bounds__(NTHR, 1) sc_main(
    const float* __restrict__ X, const float* __restrict__ Wt,
    const float* __restrict__ Bs, float* __restrict__ Out)
{
    extern __shared__ float smem[];
    float*  wsm   = smem;                                    // [ci][kh][kw][co]
    float2* rbuf2 = (float2*)(smem + WSM_FLOATS);            // [slot][ci][RST2] splat pairs
    float*  bsm   = (float*)(rbuf2 + RBUF2_ELEMS);           // [co]

    const int tile = blockIdx.x;
    const int b    = blockIdx.y;
    const int w0   = tile * TW;
    const int tid  = threadIdx.x;

    // Weights transposed: wsm[((ci*3+kh)*3+kw)*64 + co] = W[co][ci][kh][kw]
    for (int i = tid; i < Cc * Cc * 9; i += NTHR) {
        int co = i & 63; int r = i >> 6;
        int kw = r % 3; r /= 3; int kh = r % 3; int ci = r / 3;
        wsm[((ci * 3 + kh) * 3 + kw) * Cc + co] = Wt[((co * Cc + ci) * 3 + kh) * 3 + kw];
    }
    if (tid < Cc) bsm[tid] = Bs[tid];

    const float* Xb = X   + (size_t)b * Cc * Hh * Ww;
    float*       Ob = Out + (size_t)b * Cc * Hh * Ww;

    // Rows 0,1 (unchanged) -> splat pairs in slots 0,1, and copy to Out.
    for (int r = 0; r < 2; r++) {
        for (int i = tid; i < Cc * 18; i += NTHR) {
            int ci = i / 18, wi = i % 18; int w = w0 - 1 + wi;
            float v = (w >= 0 && w < Ww) ? Xb[(ci * Hh + r) * Ww + w] : 0.f;
            rbuf2[(r * Cc + ci) * RST2 + wi] = make_float2(v, v);
        }
        for (int i = tid; i < Cc * TW; i += NTHR) {
            int ci = i / TW, wq = i % TW;
            Ob[(ci * Hh + r) * Ww + w0 + wq] = Xb[(ci * Hh + r) * Ww + w0 + wq];
        }
    }

    // Thread -> (co pair, 4 output columns)
    const int co0 = (tid >> 2) * 2;
    const int wl  = (tid & 3) * 4;

    int* myflag = &g_flags[b * NT + tile];
    int* lflag  = (tile > 0)      ? &g_flags[b * NT + tile - 1] : (int*)0;
    int* rflag  = (tile < NT - 1) ? &g_flags[b * NT + tile + 1] : (int*)0;

    // Prefetch row 2 into registers (9 elems/thread covers 64*18=1152).
    float pv[9];
    #pragma unroll
    for (int k = 0; k < 9; k++) {
        int idx = tid + k * NTHR; int ci = idx / 18, wi = idx % 18;
        int w = w0 - 1 + wi;
        pv[k] = (w >= 0 && w < Ww) ? __ldg(&Xb[(ci * Hh + 2) * Ww + w]) : 0.f;
    }

    for (int pos = 2; pos < Hh; pos++) {
        const int s2 = pos % 3;            // orig row pos -> becomes updated row pos
        const int s0 = (pos + 1) % 3;      // updated row pos-2
        const int s1 = (pos + 2) % 3;      // updated row pos-1

        // Store prefetched original row `pos` (splatted) into slot s2.
        #pragma unroll
        for (int k = 0; k < 9; k++) {
            int idx = tid + k * NTHR; int ci = idx / 18, wi = idx % 18;
            rbuf2[(s2 * Cc + ci) * RST2 + wi] = make_float2(pv[k], pv[k]);
        }
        __syncthreads();

        ull acc[4] = {0ull, 0ull, 0ull, 0ull};
        const ull* b0 = (const ull*)(rbuf2 + (s0 * Cc) * RST2 + wl);
        const ull* b1 = (const ull*)(rbuf2 + (s1 * Cc) * RST2 + wl);
        const ull* b2 = (const ull*)(rbuf2 + (s2 * Cc) * RST2 + wl);
        const float* wq = wsm + co0;

        #pragma unroll 2
        for (int ci = 0; ci < Cc; ci++) {
            #pragma unroll
            for (int kh = 0; kh < 3; kh++) {
                const ull* row = (kh == 0) ? (b0 + ci * RST2)
                               : (kh == 1) ? (b1 + ci * RST2)
                                           : (b2 + ci * RST2);
                ull i0 = row[0], i1 = row[1], i2 = row[2];
                ull i3 = row[3], i4 = row[4], i5 = row[5];
                const ull* wk = (const ull*)(wq + (ci * 9 + kh * 3) * Cc);
                ull wp0 = wk[0], wp1 = wk[Cc / 2], wp2 = wk[Cc];
                ffma2(acc[0], i0, wp0); ffma2(acc[1], i1, wp0);
                ffma2(acc[2], i2, wp0); ffma2(acc[3], i3, wp0);
                ffma2(acc[0], i1, wp1); ffma2(acc[1], i2, wp1);
                ffma2(acc[2], i3, wp1); ffma2(acc[3], i4, wp1);
                ffma2(acc[0], i2, wp2); ffma2(acc[1], i3, wp2);
                ffma2(acc[2], i4, wp2); ffma2(acc[3], i5, wp2);
            }
        }

        // res = orig + tanh(y + bias); orig read from slot s2 before overwrite.
        float res0[4], res1[4];
        const float2* oc0 = rbuf2 + (s2 * Cc + co0) * RST2 + wl + 1;
        const float2* oc1 = oc0 + RST2;
        float bb0 = bsm[co0], bb1 = bsm[co0 + 1];
        #pragma unroll
        for (int j = 0; j < 4; j++) {
            float2 aj; asm("mov.b64 {%0, %1}, %2;" : "=f"(aj.x), "=f"(aj.y) : "l"(acc[j]));
            res0[j] = oc0[j].x + tanhf(aj.x + bb0);
            res1[j] = oc1[j].x + tanhf(aj.y + bb1);
        }
        __syncthreads();   // reads of slot s2 (orig) done before overwrite

        // Write updated row into slot s2 (splat, interior) and into Out.
        float2* wr0 = rbuf2 + (s2 * Cc + co0) * RST2 + wl + 1;
        #pragma unroll
        for (int j = 0; j < 4; j++) {
            wr0[j]        = make_float2(res0[j], res0[j]);
            wr0[RST2 + j] = make_float2(res1[j], res1[j]);
        }
        float* og = Ob + ((size_t)co0 * Hh + pos) * Ww + w0 + wl;
        *(float4*)og = make_float4(res0[0], res0[1], res0[2], res0[3]);
        *(float4*)(og + (size_t)Hh * Ww) = make_float4(res1[0], res1[1], res1[2], res1[3]);

        // Prefetch next original row while we publish/spin.
        if (pos + 1 < Hh) {
            #pragma unroll
            for (int k = 0; k < 9; k++) {
                int idx = tid + k * NTHR; int ci = idx / 18, wi = idx % 18;
                int w = w0 - 1 + wi;
                pv[k] = (w >= 0 && w < Ww) ? __ldg(&Xb[(ci * Hh + pos + 1) * Ww + w]) : 0.f;
            }
        }

        // Publish: stores -> fence -> barrier -> flag release.
        __threadfence();
        __syncthreads();
        if (tid == 0) atomicExch(myflag, pos);

        // Acquire neighbors' row `pos`, pull 1-column halos from Out (L2).
        if (tid == 0 && lflag)  { while (atomicAdd(lflag, 0) < pos) __nanosleep(40); __threadfence(); }
        if (tid == 32 && rflag) { while (atomicAdd(rflag, 0) < pos) __nanosleep(40); __threadfence(); }
        __syncthreads();

        if (tid < Cc) {
            if (lflag) {
                float h = __ldcg(&Ob[((size_t)tid * Hh + pos) * Ww + w0 - 1]);
                rbuf2[(s2 * Cc + tid) * RST2] = make_float2(h, h);
            }
        } else {
            int ci = tid - Cc;
            if (rflag) {
                float h = __ldcg(&Ob[((size_t)ci * Hh + pos) * Ww + w0 + TW]);
                rbuf2[(s2 * Cc + ci) * RST2 + 17] = make_float2(h, h);
            }
        }
        // next iteration's __syncthreads orders these STS before compute reads
    }
}

extern "C" void kernel_launch(void* const* d_in, const int* in_sizes, int n_in,
                              void* d_out, int out_size) {
    const float* X  = (const float*)d_in[0];
    const float* Wt = (const float*)d_in[1];
    const float* Bs = (const float*)d_in[2];
    float* Out = (float*)d_out;
    (void)in_sizes; (void)n_in; (void)out_size;

    cudaFuncSetAttribute(sc_main, cudaFuncAttributeMaxDynamicSharedMemorySize, SMEM_BYTES);

    sc_init_flags<<<1, NTHR>>>();
    sc_main<<<dim3(NT, Bb), NTHR, SMEM_BYTES>>>(X, Wt, Bs, Out);
}

// round 4
// speedup vs baseline: 1.6795x; 1.6795x over previous
#include <cuda_runtime.h>

// SequentialConv: B=8, C=64, H=192, W=256, 3x3, sequential row recurrence.
// Persistent wavefront: 8 batches x 16 width-tiles = 128 CTAs (all resident).
// Round 4: 256 threads/CTA (2 warps per SMSP) for latency hiding; scalar FFMA
// datapath (R2-proven); register prefetch of next row during publish/spin.

#define Bb 8
#define Cc 64
#define Hh 192
#define Ww 256
#define NT 16
#define TW 16
#define NTHR 256
#define RST 20         // smem row stride in floats (18 used: w0-1 .. w0+16)

#define WSM_FLOATS (Cc * Cc * 9)
#define RBUF_FLOATS (3 * Cc * RST)
#define SMEM_FLOATS (WSM_FLOATS + RBUF_FLOATS + Cc)
#define SMEM_BYTES (SMEM_FLOATS * 4)

__device__ int g_flags[Bb * NT];

__global__ void sc_init_flags() {
    int i = threadIdx.x;
    if (i < Bb * NT) g_flags[i] = 1;   // rows 0,1 are complete (unchanged)
}

__global__ void __launch_bounds__(NTHR, 1) sc_main(
    const float* __restrict__ X, const float* __restrict__ Wt,
    const float* __restrict__ Bs, float* __restrict__ Out)
{
    extern __shared__ float smem[];
    float* wsm  = smem;                      // [ci][kh][kw][co]
    float* rbuf = smem + WSM_FLOATS;         // [slot][ci][RST]
    float* bsm  = rbuf + RBUF_FLOATS;        // [co]

    const int tile = blockIdx.x;
    const int b    = blockIdx.y;
    const int w0   = tile * TW;
    const int tid  = threadIdx.x;

    // Weights transposed: wsm[((ci*3+kh)*3+kw)*64 + co] = W[co][ci][kh][kw]
    for (int i = tid; i < Cc * Cc * 9; i += NTHR) {
        int co = i & 63; int r = i >> 6;
        int kw = r % 3; r /= 3; int kh = r % 3; int ci = r / 3;
        wsm[((ci * 3 + kh) * 3 + kw) * Cc + co] = Wt[((co * Cc + ci) * 3 + kh) * 3 + kw];
    }
    if (tid < Cc) bsm[tid] = Bs[tid];

    const float* Xb = X   + (size_t)b * Cc * Hh * Ww;
    float*       Ob = Out + (size_t)b * Cc * Hh * Ww;

    // Rows 0,1 (unchanged) -> rbuf slots 0,1 (with halo), copy to Out.
    for (int r = 0; r < 2; r++) {
        for (int i = tid; i < Cc * 18; i += NTHR) {
            int ci = i / 18, wi = i % 18; int w = w0 - 1 + wi;
            float v = (w >= 0 && w < Ww) ? Xb[(ci * Hh + r) * Ww + w] : 0.f;
            rbuf[(r * Cc + ci) * RST + wi] = v;
        }
        for (int i = tid; i < Cc * TW; i += NTHR) {
            int ci = i / TW, wq = i % TW;
            Ob[(ci * Hh + r) * Ww + w0 + wq] = Xb[(ci * Hh + r) * Ww + w0 + wq];
        }
    }

    // Thread -> (2 output channels, 2 output columns)
    const int co0 = (tid >> 3) * 2;      // 32 co-groups of 2
    const int wl  = (tid & 7) * 2;       // 8 w-groups of 2

    int* myflag = &g_flags[b * NT + tile];
    int* lflag  = (tile > 0)      ? &g_flags[b * NT + tile - 1] : (int*)0;
    int* rflag  = (tile < NT - 1) ? &g_flags[b * NT + tile + 1] : (int*)0;

    // Prefetch row 2 into registers (5 elems/thread covers 64*18=1152).
    float pv[5];
    #pragma unroll
    for (int k = 0; k < 5; k++) {
        int idx = tid + k * NTHR;
        if (idx < Cc * 18) {
            int ci = idx / 18, wi = idx % 18; int w = w0 - 1 + wi;
            pv[k] = (w >= 0 && w < Ww) ? __ldg(&Xb[(ci * Hh + 2) * Ww + w]) : 0.f;
        }
    }

    for (int pos = 2; pos < Hh; pos++) {
        const int s2 = pos % 3;            // orig row pos -> becomes updated row pos
        const int s0 = (pos + 1) % 3;      // updated row pos-2
        const int s1 = (pos + 2) % 3;      // updated row pos-1

        // Store prefetched original row `pos` into slot s2.
        #pragma unroll
        for (int k = 0; k < 5; k++) {
            int idx = tid + k * NTHR;
            if (idx < Cc * 18) {
                int ci = idx / 18, wi = idx % 18;
                rbuf[(s2 * Cc + ci) * RST + wi] = pv[k];
            }
        }
        __syncthreads();

        float acc0[2] = {0.f, 0.f};
        float acc1[2] = {0.f, 0.f};
        const float* base0 = rbuf + s0 * Cc * RST + wl;
        const float* base1 = rbuf + s1 * Cc * RST + wl;
        const float* base2 = rbuf + s2 * Cc * RST + wl;
        const float* wq    = wsm + co0;

        #pragma unroll 4
        for (int ci = 0; ci < Cc; ci++) {
            const float* rr0 = base0 + ci * RST;
            const float* rr1 = base1 + ci * RST;
            const float* rr2 = base2 + ci * RST;
            #pragma unroll
            for (int kh = 0; kh < 3; kh++) {
                const float* row = (kh == 0) ? rr0 : (kh == 1) ? rr1 : rr2;
                float in0 = row[0], in1 = row[1], in2 = row[2], in3 = row[3];
                const float* wk = wq + (ci * 9 + kh * 3) * Cc;
                float2 wv0 = *(const float2*)(wk);
                float2 wv1 = *(const float2*)(wk + Cc);
                float2 wv2 = *(const float2*)(wk + 2 * Cc);
                acc0[0] += in0 * wv0.x; acc1[0] += in0 * wv0.y;
                acc0[1] += in1 * wv0.x; acc1[1] += in1 * wv0.y;
                acc0[0] += in1 * wv1.x; acc1[0] += in1 * wv1.y;
                acc0[1] += in2 * wv1.x; acc1[1] += in2 * wv1.y;
                acc0[0] += in2 * wv2.x; acc1[0] += in2 * wv2.y;
                acc0[1] += in3 * wv2.x; acc1[1] += in3 * wv2.y;
            }
        }

        // res = orig + tanh(y + bias); orig read from slot s2 before overwrite.
        float res0[2], res1[2];
        const float* ocb = rbuf + s2 * Cc * RST;
        float bb0 = bsm[co0], bb1 = bsm[co0 + 1];
        #pragma unroll
        for (int j = 0; j < 2; j++) {
            float o0 = ocb[co0 * RST + wl + 1 + j];
            float o1 = ocb[(co0 + 1) * RST + wl + 1 + j];
            res0[j] = o0 + tanhf(acc0[j] + bb0);
            res1[j] = o1 + tanhf(acc1[j] + bb1);
        }
        __syncthreads();   // reads of slot s2 (orig) done before overwrite

        // Write updated row into slot s2 (interior) and into Out.
        float* wr0 = rbuf + (s2 * Cc + co0) * RST + wl + 1;
        wr0[0] = res0[0]; wr0[1] = res0[1];
        wr0[RST] = res1[0]; wr0[RST + 1] = res1[1];

        float* og = Ob + ((size_t)co0 * Hh + pos) * Ww + w0 + wl;
        *(float2*)og = make_float2(res0[0], res0[1]);
        *(float2*)(og + (size_t)Hh * Ww) = make_float2(res1[0], res1[1]);

        // Prefetch next original row while we publish/spin.
        if (pos + 1 < Hh) {
            #pragma unroll
            for (int k = 0; k < 5; k++) {
                int idx = tid + k * NTHR;
                if (idx < Cc * 18) {
                    int ci = idx / 18, wi = idx % 18; int w = w0 - 1 + wi;
                    pv[k] = (w >= 0 && w < Ww) ? __ldg(&Xb[(ci * Hh + pos + 1) * Ww + w]) : 0.f;
                }
            }
        }

        // Publish: stores -> fence -> barrier -> flag release.
        __threadfence();
        __syncthreads();
        if (tid == 0) atomicExch(myflag, pos);

        // Acquire neighbors' row `pos`, pull 1-column halos from Out (L2).
        if (tid == 0 && lflag)  { while (atomicAdd(lflag, 0) < pos) __nanosleep(40); __threadfence(); }
        if (tid == 32 && rflag) { while (atomicAdd(rflag, 0) < pos) __nanosleep(40); __threadfence(); }
        __syncthreads();

        if (tid < Cc) {
            if (lflag)
                rbuf[(s2 * Cc + tid) * RST] =
                    __ldcg(&Ob[((size_t)tid * Hh + pos) * Ww + w0 - 1]);
        } else if (tid < 2 * Cc) {
            int ci = tid - Cc;
            if (rflag)
                rbuf[(s2 * Cc + ci) * RST + 17] =
                    __ldcg(&Ob[((size_t)ci * Hh + pos) * Ww + w0 + TW]);
        }
        // next iteration's __syncthreads orders these STS before compute reads
    }
}

extern "C" void kernel_launch(void* const* d_in, const int* in_sizes, int n_in,
                              void* d_out, int out_size) {
    const float* X  = (const float*)d_in[0];
    const float* Wt = (const float*)d_in[1];
    const float* Bs = (const float*)d_in[2];
    float* Out = (float*)d_out;
    (void)in_sizes; (void)n_in; (void)out_size;

    cudaFuncSetAttribute(sc_main, cudaFuncAttributeMaxDynamicSharedMemorySize, SMEM_BYTES);

    sc_init_flags<<<1, 128>>>();
    sc_main<<<dim3(NT, Bb), NTHR, SMEM_BYTES>>>(X, Wt, Bs, Out);
}